// round 12
// baseline (speedup 1.0000x reference)
#include <cuda_runtime.h>
#include <cuda_fp16.h>
#include <math.h>
#include <stdint.h>

#define NN 50000
#define NE 640000
#define RR 8
#define DD 128
#define NRSEG (NN*RR)
#define NBLK ((NRSEG + 1023)/1024)

// ---------------- scratch (device globals; no allocations allowed) ----------
__device__ int    g_cnt[NRSEG];          // zero at load; self-zeroed by k_scatter
__device__ int    g_off[NRSEG];
__device__ int    g_cur[NRSEG];
__device__ unsigned long long g_tstat[NBLK];  // lookback flags; reset by k_scatter
__device__ int2   g_sd[NE + 32];         // (src, dst) CSR order; +32 pad for
                                         // guard-free 32-wide batch reads
__device__ float  g_h[NN*DD];
__device__ __half g_W1h[(RR+1)*DD*DD];   // [chunk][n][k-permuted] half
__device__ __half g_W2h[(RR+1)*64*DD];

// k-permutation within each 16-group: slot order packs (2t,2t+1,2t+8,2t+9)
// adjacent so one LDS.64 yields both fp16-MMA fragments.
__device__ __forceinline__ int slot16(int c) {
    return ((c & 7) >> 1)*4 + (c & 1) + ((c & 8) >> 3)*2;
}

// ---------------- prelude: hist + weight cvt/permute fused -------------------
// seg ordering is RELATION-MAJOR: seg = rel*NN + node, so each row-block x rel
// owns one contiguous edge slice sorted by dst.
__global__ void k_pre(const int* __restrict__ dst, const int* __restrict__ typ,
                      const float* __restrict__ W1, const float* __restrict__ r1,
                      const float* __restrict__ W2, const float* __restrict__ r2) {
    const int HB = (NE + 255)/256;
    const int T1 = ((RR+1)*DD*DD + 255)/256;
    int b = blockIdx.x;
    if (b < HB) {
        int e = b*256 + threadIdx.x;
        if (e < NE) atomicAdd(&g_cnt[typ[e]*NN + dst[e]], 1);
    } else if (b < HB + T1) {
        int idx = (b - HB)*256 + threadIdx.x;
        if (idx < (RR+1)*DD*DD) {
            int chunk = idx / (DD*DD);
            int rem   = idx - chunk*(DD*DD);
            int n = rem >> 7, k = rem & 127;
            float v = (chunk < RR) ? W1[(size_t)chunk*DD*DD + (size_t)k*DD + n]
                                   : r1[(size_t)k*DD + n];
            g_W1h[(size_t)chunk*DD*DD + n*DD + (k & ~15) + slot16(k & 15)] =
                __float2half_rn(v);
        }
    } else {
        int idx = (b - HB - T1)*256 + threadIdx.x;
        if (idx < (RR+1)*64*DD) {
            int chunk = idx / (64*DD);
            int rem   = idx - chunk*(64*DD);
            int n = rem >> 7, k = rem & 127;
            float v = (chunk < RR) ? W2[(size_t)chunk*DD*64 + (size_t)k*64 + n]
                                   : r2[(size_t)k*64 + n];
            g_W2h[(size_t)chunk*64*DD + n*DD + (k & ~15) + slot16(k & 15)] =
                __float2half_rn(v);
        }
    }
}

// ---------------- single-pass decoupled-lookback scan ------------------------
__global__ void __launch_bounds__(1024)
k_scan() {
    __shared__ int swarp[32];
    __shared__ int s_prefix;
    const int tid  = threadIdx.x;
    const int lane = tid & 31;
    const int wid  = tid >> 5;
    const int b    = blockIdx.x;
    const int i    = b*1024 + tid;

    int v = (i < NRSEG) ? g_cnt[i] : 0;

    int x = v;
    #pragma unroll
    for (int d = 1; d < 32; d <<= 1) {
        int t = __shfl_up_sync(0xffffffffu, x, d);
        if (lane >= d) x += t;
    }
    if (lane == 31) swarp[wid] = x;
    __syncthreads();
    if (wid == 0) {
        int y = swarp[lane];
        #pragma unroll
        for (int d = 1; d < 32; d <<= 1) {
            int t = __shfl_up_sync(0xffffffffu, y, d);
            if (lane >= d) y += t;
        }
        swarp[lane] = y;
    }
    __syncthreads();
    int incl = x + ((wid > 0) ? swarp[wid-1] : 0);
    int blocksum = swarp[31];

    if (tid == 0) {
        if (b == 0) {
            atomicExch(&g_tstat[0], (2ULL<<32) | (unsigned)blocksum);
            s_prefix = 0;
        } else {
            atomicExch(&g_tstat[b], (1ULL<<32) | (unsigned)blocksum);
            int run = 0;
            int j = b - 1;
            while (true) {
                unsigned long long f = atomicAdd(&g_tstat[j], 0ULL);
                unsigned st = (unsigned)(f >> 32);
                if (st == 0) { __nanosleep(40); continue; }
                run += (int)(unsigned)(f & 0xffffffffu);
                if (st == 2) break;
                --j;
            }
            atomicExch(&g_tstat[b], (2ULL<<32) | (unsigned)(run + blocksum));
            s_prefix = run;
        }
    }
    __syncthreads();
    if (i < NRSEG) {
        int o = s_prefix + incl - v;
        g_off[i] = o;
        g_cur[i] = o;
    }
}

__global__ void k_scatter(const int* __restrict__ src, const int* __restrict__ dst,
                          const int* __restrict__ typ) {
    int e = blockIdx.x*blockDim.x + threadIdx.x;
    if (e < NE) {
        int d = dst[e];
        int seg = typ[e]*NN + d;
        int pos = atomicAdd(&g_cur[seg], 1);
        g_sd[pos] = make_int2(src[e], d);
    }
    if (e < 32)    g_sd[NE + e] = make_int2(0, 0);   // deterministic pad
    if (e < NRSEG) g_cnt[e] = 0;
    if (e < NBLK)  g_tstat[e] = 0ULL;
}

// ---------------- fused aggregate + GEMM layer (fp16 MMA) -------------------
__device__ __forceinline__ void mma_f16(float& c0, float& c1, float& c2, float& c3,
                                        uint32_t a0, uint32_t a1, uint32_t a2, uint32_t a3,
                                        uint32_t b0, uint32_t b1) {
    asm volatile(
        "mma.sync.aligned.m16n8k16.row.col.f32.f16.f16.f32 "
        "{%0,%1,%2,%3},{%4,%5,%6,%7},{%8,%9},{%0,%1,%2,%3};"
        : "+f"(c0), "+f"(c1), "+f"(c2), "+f"(c3)
        : "r"(a0), "r"(a1), "r"(a2), "r"(a3), "r"(b0), "r"(b1));
}

__device__ __forceinline__ uint32_t pack_h2(float x, float y) {
    __half2 h = __floats2half2_rn(x, y);
    return *reinterpret_cast<uint32_t*>(&h);
}
__device__ __forceinline__ float2 unpack_h2(uint32_t u) {
    __half2 h = *reinterpret_cast<__half2*>(&u);
    return __half22float2(h);
}

// CTA = 128 nodes, 512 threads, 16 warps, 2 CTAs/SM (32 warps/SM, occ 50%).
// Gather: warp w gathers rows [8w, 8w+8). Inner loop is a BRANCH-FREE,
// fully-unrolled 32-iteration batch (tail lanes carry a sentinel record
// that accumulates into a scratch sA row) so ptxas software-pipelines the
// x-row gathers at MLP ~4-8.
// MMA:    warp w computes rows [16*(w&7), +16) x cols [(w>>3)*O/2, +O/2).
template<int O, bool SIG>
__global__ void __launch_bounds__(512, 2)
k_layer(const float* __restrict__ in,
        const __half* __restrict__ Wh,    // [9][O][DD] half, k-permuted
        const float* __restrict__ bias,
        float* __restrict__ out) {
    constexpr int TM = 128;
    constexpr int NT = 512;
    constexpr int WP = 72;     // half2 words per row (64 data + 8 pad)
    constexpr int O2 = O/2;

    extern __shared__ uint32_t smem[];
    uint32_t* sA = smem;                 // (TM+1) * WP  (row TM = scratch)
    uint32_t* sB = smem + (TM+1)*WP;     // O * WP

    const int tid  = threadIdx.x;
    const int lane = tid & 31;
    const int wid  = tid >> 5;
    const int tile = blockIdx.x * TM;

    float acc[O2/8][4];
    #pragma unroll
    for (int n8 = 0; n8 < O2/8; ++n8) {
        acc[n8][0] = 0.f; acc[n8][1] = 0.f; acc[n8][2] = 0.f; acc[n8][3] = 0.f;
    }

    const int g  = lane >> 2;
    const int tg = lane & 3;
    const int mrow = (wid & 7) * 16;   // MMA row block
    const int ncol = (wid >> 3) * O2;  // MMA col block (sB row offset)
    const int grow = wid * 8;          // gather row block (8 rows)
    // lane's two half2 store slots (natural cols 4l..4l+3 under permutation)
    const int wbase = (lane >> 2)*8 + ((lane & 1) << 2) + ((lane & 2) >> 1);
    const float* in_l = in + (lane << 2);    // lane-fixed column base

    for (int r = 0; r < RR + 1; ++r) {
        __syncthreads();   // prev chunk's MMA done reading sA/sB
        // ---- fill sB: pure half2 copy (pre-permuted in k_pre)
        {
            const uint32_t* Wp = reinterpret_cast<const uint32_t*>(
                Wh + (size_t)r*O*DD);
            #pragma unroll 4
            for (int idx = tid; idx < O*DD/2; idx += NT) {
                int n = idx >> 6, kk = idx & 63;
                sB[n*WP + kk] = Wp[idx];
            }
        }
        __syncthreads();   // sB ready; prev MMA reads of sA drained

        // ================= gather: warp -> 8 rows, branch-free 32-batches ====
        if (r < RR) {
            // zero warp's 8 rows
            for (int w = lane; w < 8*WP; w += 32) sA[grow*WP + w] = 0u;

            // lane l (l<=8) holds boundary offset for row grow+l
            int bidx = r*NN + min(tile + grow + min(lane, 8), NN);
            int offv = (bidx < NRSEG) ? g_off[bidx] : NE;
            int es = __shfl_sync(0xffffffffu, offv, 0);
            int ee = __shfl_sync(0xffffffffu, offv, 8);

            float4 v = make_float4(0.f,0.f,0.f,0.f);
            int currow = -1;
            for (int base = es; base < ee; base += 32) {
                const int m = ee - base;     // lanes >= m become sentinels
                // stage edge records: ONE coalesced LDG.64 (pad-safe)
                int2 sdl = g_sd[base + lane];
                if (lane >= m) { sdl.x = 0; sdl.y = tile + TM; }  // scratch row

                // straight-line 32 iterations, no guards -> deep pipelining
                #pragma unroll
                for (int j = 0; j < 32; ++j) {
                    int src = __shfl_sync(0xffffffffu, sdl.x, j);
                    int row = __shfl_sync(0xffffffffu, sdl.y, j);
                    const float4 xv = *reinterpret_cast<const float4*>(
                        in_l + (size_t)src*DD);
                    bool fresh = (row != currow);
                    currow = row;
                    v.x = (fresh ? 0.f : v.x) + xv.x;
                    v.y = (fresh ? 0.f : v.y) + xv.y;
                    v.z = (fresh ? 0.f : v.z) + xv.z;
                    v.w = (fresh ? 0.f : v.w) + xv.w;
                    int rw = (currow - tile)*WP;
                    sA[rw + wbase]     = pack_h2(v.x, v.y);   // last write wins
                    sA[rw + wbase + 2] = pack_h2(v.z, v.w);
                }
            }

            // post-pass: scale rows by 1/cnt (thread-local slots)
            #pragma unroll
            for (int i = 0; i < 8; ++i) {
                int c = __shfl_sync(0xffffffffu, offv, i+1)
                      - __shfl_sync(0xffffffffu, offv, i);
                if (c > 0) {
                    float inv = 1.f/(float)c;
                    int idx = (grow+i)*WP + wbase;
                    float2 u0 = unpack_h2(sA[idx]);
                    float2 u1 = unpack_h2(sA[idx+2]);
                    sA[idx]   = pack_h2(u0.x*inv, u0.y*inv);
                    sA[idx+2] = pack_h2(u1.x*inv, u1.y*inv);
                }
            }
        } else {
            // root chunk: direct copy of input tile
            #pragma unroll
            for (int ii = 0; ii < 8; ++ii) {
                int node = tile + grow + ii;
                float4 xv = make_float4(0.f,0.f,0.f,0.f);
                if (node < NN)
                    xv = *reinterpret_cast<const float4*>(
                        in_l + (size_t)node*DD);
                int idx = (grow+ii)*WP + wbase;
                sA[idx]   = pack_h2(xv.x, xv.y);
                sA[idx+2] = pack_h2(xv.z, xv.w);
            }
        }
        __syncthreads();   // sA tile complete (cross-warp rows)

        // ================= MMA (fp16, fp32 accum) =================
        #pragma unroll
        for (int k16 = 0; k16 < DD/16; ++k16) {
            const uint2 aLo = *reinterpret_cast<const uint2*>(
                &sA[(mrow + g    )*WP + k16*8 + tg*2]);   // (a0, a2)
            const uint2 aHi = *reinterpret_cast<const uint2*>(
                &sA[(mrow + g + 8)*WP + k16*8 + tg*2]);   // (a1, a3)
            #pragma unroll
            for (int n8 = 0; n8 < O2/8; ++n8) {
                const uint2 bb = *reinterpret_cast<const uint2*>(
                    &sB[(ncol + n8*8 + g)*WP + k16*8 + tg*2]);  // (b0, b1)
                mma_f16(acc[n8][0], acc[n8][1], acc[n8][2], acc[n8][3],
                        aLo.x, aHi.x, aLo.y, aHi.y, bb.x, bb.y);
            }
        }
    }

    // ---- epilogue: bias (+ sigmoid), write out
    const int r0 = tile + mrow + g;
    const int r1 = r0 + 8;
    #pragma unroll
    for (int n8 = 0; n8 < O2/8; ++n8) {
        int c0 = ncol + n8*8 + 2*tg;
        int c1 = c0 + 1;
        float bz0 = bias[c0], bz1 = bias[c1];
        float v00 = acc[n8][0] + bz0;
        float v01 = acc[n8][1] + bz1;
        float v10 = acc[n8][2] + bz0;
        float v11 = acc[n8][3] + bz1;
        if (SIG) {
            v00 = 1.f/(1.f + __expf(-v00));
            v01 = 1.f/(1.f + __expf(-v01));
            v10 = 1.f/(1.f + __expf(-v10));
            v11 = 1.f/(1.f + __expf(-v11));
        }
        if (r0 < NN) { out[(size_t)r0*O + c0] = v00; out[(size_t)r0*O + c1] = v01; }
        if (r1 < NN) { out[(size_t)r1*O + c0] = v10; out[(size_t)r1*O + c1] = v11; }
    }
}

// ---------------- launch ----------------------------------------------------
extern "C" void kernel_launch(void* const* d_in, const int* in_sizes, int n_in,
                              void* d_out, int out_size) {
    const float* x    = (const float*)d_in[0];
    const int*   esrc = (const int*)  d_in[1];
    const int*   edst = (const int*)  d_in[2];
    const int*   etyp = (const int*)  d_in[3];
    const float* W1   = (const float*)d_in[4];
    const float* r1   = (const float*)d_in[5];
    const float* b1   = (const float*)d_in[6];
    const float* W2   = (const float*)d_in[7];
    const float* r2   = (const float*)d_in[8];
    const float* b2   = (const float*)d_in[9];
    float* out = (float*)d_out;

    constexpr int SMEM_L1 = (128 + 1 + 128) * 72 * 4;  // 74016 B -> 2 CTAs/SM
    constexpr int SMEM_L2 = (128 + 1 +  64) * 72 * 4;  // 55584 B -> 2 CTAs/SM
    cudaFuncSetAttribute(k_layer<128,false>, cudaFuncAttributeMaxDynamicSharedMemorySize, SMEM_L1);
    cudaFuncSetAttribute(k_layer< 64,true >, cudaFuncAttributeMaxDynamicSharedMemorySize, SMEM_L2);

    void* p = nullptr;
    cudaGetSymbolAddress(&p, g_h);   float*  h   = (float*)p;
    cudaGetSymbolAddress(&p, g_W1h); __half* w1h = (__half*)p;
    cudaGetSymbolAddress(&p, g_W2h); __half* w2h = (__half*)p;

    const int HB = (NE + 255)/256;
    const int T1 = ((RR+1)*DD*DD + 255)/256;
    const int T2 = ((RR+1)*64*DD + 255)/256;
    k_pre    <<<HB + T1 + T2,    256>>>(edst, etyp, W1, r1, W2, r2);   // launch 0
    k_scan   <<<NBLK,           1024>>>();                              // launch 1
    k_scatter<<<(NE+255)/256,    256>>>(esrc, edst, etyp);              // launch 2

    k_layer<128,false><<<(NN+127)/128, 512, SMEM_L1>>>(x, w1h, b1, h);  // launch 3 (profiled)
    k_layer< 64,true ><<<(NN+127)/128, 512, SMEM_L2>>>(h, w2h, b2, out);// launch 4
}

// round 13
// speedup vs baseline: 1.3816x; 1.3816x over previous
#include <cuda_runtime.h>
#include <cuda_fp16.h>
#include <math.h>
#include <stdint.h>

#define NN 50000
#define NE 640000
#define RR 8
#define DD 128
#define NRSEG (NN*RR)
#define NBLK ((NRSEG + 1023)/1024)

// ---------------- scratch (device globals; no allocations allowed) ----------
__device__ int    g_cnt[NRSEG];          // zero at load; self-zeroed by k_scatter
__device__ int    g_off[NRSEG];
__device__ int    g_cur[NRSEG];
__device__ unsigned long long g_tstat[NBLK];  // lookback flags; reset by k_scatter
__device__ int2   g_sd[NE];              // (src, dst) packed, CSR order
__device__ __half g_xh[NN*DD];           // x pre-converted to half
__device__ __half g_h[NN*DD];            // layer1 output (half)
__device__ __half g_W1h[(RR+1)*DD*DD];   // [chunk][n][k-permuted] half
__device__ __half g_W2h[(RR+1)*64*DD];

// k-permutation within each 16-group: slot order packs (2t,2t+1,2t+8,2t+9)
// adjacent so one LDS.64 yields both fp16-MMA fragments.
__device__ __forceinline__ int slot16(int c) {
    return ((c & 7) >> 1)*4 + (c & 1) + ((c & 8) >> 3)*2;
}

#define CP_ASYNC16(smem_u32, gptr) \
    asm volatile("cp.async.cg.shared.global [%0], [%1], 16;" \
                 :: "r"(smem_u32), "l"(gptr) : "memory")
#define CP_COMMIT()  asm volatile("cp.async.commit_group;" ::: "memory")
#define CP_WAIT0()   asm volatile("cp.async.wait_group 0;" ::: "memory")

// ---------------- prelude: hist + weight cvt/permute + x cvt fused -----------
// seg ordering is RELATION-MAJOR: seg = rel*NN + node, so each row-block x rel
// owns one contiguous edge slice sorted by dst.
__global__ void k_pre(const int* __restrict__ dst, const int* __restrict__ typ,
                      const float* __restrict__ x,
                      const float* __restrict__ W1, const float* __restrict__ r1,
                      const float* __restrict__ W2, const float* __restrict__ r2) {
    const int HB = (NE + 255)/256;
    const int T1 = ((RR+1)*DD*DD + 255)/256;
    const int T2 = ((RR+1)*64*DD + 255)/256;
    int b = blockIdx.x;
    if (b < HB) {
        int e = b*256 + threadIdx.x;
        if (e < NE) atomicAdd(&g_cnt[typ[e]*NN + dst[e]], 1);
    } else if (b < HB + T1) {
        int idx = (b - HB)*256 + threadIdx.x;
        if (idx < (RR+1)*DD*DD) {
            int chunk = idx / (DD*DD);
            int rem   = idx - chunk*(DD*DD);
            int n = rem >> 7, k = rem & 127;
            float v = (chunk < RR) ? W1[(size_t)chunk*DD*DD + (size_t)k*DD + n]
                                   : r1[(size_t)k*DD + n];
            g_W1h[(size_t)chunk*DD*DD + n*DD + (k & ~15) + slot16(k & 15)] =
                __float2half_rn(v);
        }
    } else if (b < HB + T1 + T2) {
        int idx = (b - HB - T1)*256 + threadIdx.x;
        if (idx < (RR+1)*64*DD) {
            int chunk = idx / (64*DD);
            int rem   = idx - chunk*(64*DD);
            int n = rem >> 7, k = rem & 127;
            float v = (chunk < RR) ? W2[(size_t)chunk*DD*64 + (size_t)k*64 + n]
                                   : r2[(size_t)k*64 + n];
            g_W2h[(size_t)chunk*64*DD + n*DD + (k & ~15) + slot16(k & 15)] =
                __float2half_rn(v);
        }
    } else {
        // x -> half, 4 floats per thread
        int idx = (b - HB - T1 - T2)*256 + threadIdx.x;
        if (idx < NN*DD/4) {
            float4 xv = reinterpret_cast<const float4*>(x)[idx];
            __half2* o = reinterpret_cast<__half2*>(g_xh) + idx*2;
            o[0] = __floats2half2_rn(xv.x, xv.y);
            o[1] = __floats2half2_rn(xv.z, xv.w);
        }
    }
}

// ---------------- single-pass decoupled-lookback scan ------------------------
__global__ void __launch_bounds__(1024)
k_scan() {
    __shared__ int swarp[32];
    __shared__ int s_prefix;
    const int tid  = threadIdx.x;
    const int lane = tid & 31;
    const int wid  = tid >> 5;
    const int b    = blockIdx.x;
    const int i    = b*1024 + tid;

    int v = (i < NRSEG) ? g_cnt[i] : 0;

    int x = v;
    #pragma unroll
    for (int d = 1; d < 32; d <<= 1) {
        int t = __shfl_up_sync(0xffffffffu, x, d);
        if (lane >= d) x += t;
    }
    if (lane == 31) swarp[wid] = x;
    __syncthreads();
    if (wid == 0) {
        int y = swarp[lane];
        #pragma unroll
        for (int d = 1; d < 32; d <<= 1) {
            int t = __shfl_up_sync(0xffffffffu, y, d);
            if (lane >= d) y += t;
        }
        swarp[lane] = y;
    }
    __syncthreads();
    int incl = x + ((wid > 0) ? swarp[wid-1] : 0);
    int blocksum = swarp[31];

    if (tid == 0) {
        if (b == 0) {
            atomicExch(&g_tstat[0], (2ULL<<32) | (unsigned)blocksum);
            s_prefix = 0;
        } else {
            atomicExch(&g_tstat[b], (1ULL<<32) | (unsigned)blocksum);
            int run = 0;
            int j = b - 1;
            while (true) {
                unsigned long long f = atomicAdd(&g_tstat[j], 0ULL);
                unsigned st = (unsigned)(f >> 32);
                if (st == 0) { __nanosleep(40); continue; }
                run += (int)(unsigned)(f & 0xffffffffu);
                if (st == 2) break;
                --j;
            }
            atomicExch(&g_tstat[b], (2ULL<<32) | (unsigned)(run + blocksum));
            s_prefix = run;
        }
    }
    __syncthreads();
    if (i < NRSEG) {
        int o = s_prefix + incl - v;
        g_off[i] = o;
        g_cur[i] = o;
    }
}

__global__ void k_scatter(const int* __restrict__ src, const int* __restrict__ dst,
                          const int* __restrict__ typ) {
    int e = blockIdx.x*blockDim.x + threadIdx.x;
    if (e < NE) {
        int d = dst[e];
        int seg = typ[e]*NN + d;
        int pos = atomicAdd(&g_cur[seg], 1);
        g_sd[pos] = make_int2(src[e], d);
    }
    if (e < NRSEG) g_cnt[e] = 0;
    if (e < NBLK)  g_tstat[e] = 0ULL;
}

// ---------------- fused aggregate + GEMM layer (fp16 MMA) -------------------
__device__ __forceinline__ void mma_f16(float& c0, float& c1, float& c2, float& c3,
                                        uint32_t a0, uint32_t a1, uint32_t a2, uint32_t a3,
                                        uint32_t b0, uint32_t b1) {
    asm volatile(
        "mma.sync.aligned.m16n8k16.row.col.f32.f16.f16.f32 "
        "{%0,%1,%2,%3},{%4,%5,%6,%7},{%8,%9},{%0,%1,%2,%3};"
        : "+f"(c0), "+f"(c1), "+f"(c2), "+f"(c3)
        : "r"(a0), "r"(a1), "r"(a2), "r"(a3), "r"(b0), "r"(b1));
}

__device__ __forceinline__ uint32_t pack_h2(float x, float y) {
    __half2 h = __floats2half2_rn(x, y);
    return *reinterpret_cast<uint32_t*>(&h);
}
__device__ __forceinline__ float2 unpack_h2(uint32_t u) {
    __half2 h = *reinterpret_cast<__half2*>(&u);
    return __half22float2(h);
}

// CTA = 128 nodes, 512 threads, 16 warps, 2 CTAs/SM (32 warps/SM, occ 50%).
// in/out node features are HALF (pre-converted) -> gather row = LDG.64/lane.
// sB is double-buffered and filled with cp.async for chunk r+1 while chunk r
// gathers + MMAs. Gather: warp w gathers rows [8w, 8w+8) (R10 guarded loop).
// MMA: warp w computes rows [16*(w&7), +16) x cols [(w>>3)*O/2, +O/2).
template<int O, bool SIG, typename OutT>
__global__ void __launch_bounds__(512, 2)
k_layer(const __half* __restrict__ in,
        const __half* __restrict__ Wh,    // [9][O][DD] half, k-permuted
        const float* __restrict__ bias,
        OutT* __restrict__ out) {
    constexpr int TM = 128;
    constexpr int NT = 512;
    constexpr int WP = 72;     // half2 words per row (64 data + 8 pad)
    constexpr int O2 = O/2;

    extern __shared__ uint32_t smem[];
    uint32_t* sA = smem;                 // TM * WP
    uint32_t* sB0 = smem + TM*WP;        // O * WP (buffer 0)
    uint32_t* sB1 = sB0 + O*WP;          // O * WP (buffer 1)
    const uint32_t smem_u32 = (uint32_t)__cvta_generic_to_shared(smem);

    const int tid  = threadIdx.x;
    const int lane = tid & 31;
    const int wid  = tid >> 5;
    const int tile = blockIdx.x * TM;

    float acc[O2/8][4];
    #pragma unroll
    for (int n8 = 0; n8 < O2/8; ++n8) {
        acc[n8][0] = 0.f; acc[n8][1] = 0.f; acc[n8][2] = 0.f; acc[n8][3] = 0.f;
    }

    const int g  = lane >> 2;
    const int tg = lane & 3;
    const int mrow = (wid & 7) * 16;   // MMA row block
    const int ncol = (wid >> 3) * O2;  // MMA col block (sB row offset)
    const int grow = wid * 8;          // gather row block (8 rows)
    // lane's two half2 store slots (natural cols 4l..4l+3 under permutation)
    const int wbase = (lane >> 2)*8 + ((lane & 1) << 2) + ((lane & 2) >> 1);
    const __half* in_l = in + (lane << 2);    // lane-fixed column base

    // ---- cp.async fill helper (16B units): row n = u>>4, sub = u&15
    auto fill_sB = [&](int bufsel, int r) {
        const __half* Wp = Wh + (size_t)r*O*DD;
        uint32_t sbase = smem_u32 + (TM*WP + bufsel*O*WP)*4;
        #pragma unroll
        for (int u = tid; u < O*16; u += NT) {
            int n = u >> 4, sub = u & 15;
            CP_ASYNC16(sbase + (n*WP + sub*4)*4, Wp + n*DD + sub*8);
        }
        CP_COMMIT();
    };

    // prologue: prefetch chunk 0 into buffer 0
    fill_sB(0, 0);
    int cur = 0;

    for (int r = 0; r < RR + 1; ++r) {
        CP_WAIT0();
        __syncthreads();   // sB[cur] visible; prev MMA done reading sA & sB[cur^1]
        if (r < RR) fill_sB(cur ^ 1, r + 1);   // overlap with gather + MMA

        // ================= gather: warp -> 8 rows =================
        if (r < RR) {
            // zero warp's 8 rows
            for (int w = lane; w < 8*WP; w += 32) sA[grow*WP + w] = 0u;

            // lane l (l<=8) holds boundary offset for row grow+l
            int bidx = r*NN + min(tile + grow + min(lane, 8), NN);
            int offv = (bidx < NRSEG) ? g_off[bidx] : NE;
            int es = __shfl_sync(0xffffffffu, offv, 0);
            int ee = __shfl_sync(0xffffffffu, offv, 8);

            float4 v = make_float4(0.f,0.f,0.f,0.f);
            int currow = -1;
            for (int base = es; base < ee; base += 32) {
                const int m = min(ee - base, 32);
                // stage edge records: ONE coalesced LDG.64 for the warp
                int2 sdl = make_int2(0, 0);
                if (lane < m) sdl = g_sd[base + lane];
                // inner loop: register-resident addresses, LDG.64 rows
                #pragma unroll 4
                for (int j = 0; j < m; ++j) {
                    int src = __shfl_sync(0xffffffffu, sdl.x, j);
                    int row = __shfl_sync(0xffffffffu, sdl.y, j);
                    const uint2 u = *reinterpret_cast<const uint2*>(
                        in_l + (size_t)src*DD);
                    float2 lo = unpack_h2(u.x);
                    float2 hi = unpack_h2(u.y);
                    bool fresh = (row != currow);
                    currow = row;
                    v.x = (fresh ? 0.f : v.x) + lo.x;
                    v.y = (fresh ? 0.f : v.y) + lo.y;
                    v.z = (fresh ? 0.f : v.z) + hi.x;
                    v.w = (fresh ? 0.f : v.w) + hi.y;
                    int rw = (currow - tile)*WP;
                    sA[rw + wbase]     = pack_h2(v.x, v.y);   // last write wins
                    sA[rw + wbase + 2] = pack_h2(v.z, v.w);
                }
            }

            // post-pass: scale rows by 1/cnt (thread-local slots)
            #pragma unroll
            for (int i = 0; i < 8; ++i) {
                int c = __shfl_sync(0xffffffffu, offv, i+1)
                      - __shfl_sync(0xffffffffu, offv, i);
                if (c > 0) {
                    float inv = 1.f/(float)c;
                    int idx = (grow+i)*WP + wbase;
                    float2 u0 = unpack_h2(sA[idx]);
                    float2 u1 = unpack_h2(sA[idx+2]);
                    sA[idx]   = pack_h2(u0.x*inv, u0.y*inv);
                    sA[idx+2] = pack_h2(u1.x*inv, u1.y*inv);
                }
            }
        } else {
            // root chunk: direct half copy of input tile (no cvt needed)
            #pragma unroll
            for (int ii = 0; ii < 8; ++ii) {
                int node = tile + grow + ii;
                uint2 u = make_uint2(0u, 0u);
                if (node < NN)
                    u = *reinterpret_cast<const uint2*>(
                        in_l + (size_t)node*DD);
                int idx = (grow+ii)*WP + wbase;
                sA[idx]   = u.x;
                sA[idx+2] = u.y;
            }
        }
        __syncthreads();   // sA tile complete (cross-warp rows)

        // ================= MMA (fp16, fp32 accum) =================
        const uint32_t* sBc = (cur == 0) ? sB0 : sB1;
        #pragma unroll
        for (int k16 = 0; k16 < DD/16; ++k16) {
            const uint2 aLo = *reinterpret_cast<const uint2*>(
                &sA[(mrow + g    )*WP + k16*8 + tg*2]);   // (a0, a2)
            const uint2 aHi = *reinterpret_cast<const uint2*>(
                &sA[(mrow + g + 8)*WP + k16*8 + tg*2]);   // (a1, a3)
            #pragma unroll
            for (int n8 = 0; n8 < O2/8; ++n8) {
                const uint2 bb = *reinterpret_cast<const uint2*>(
                    &sBc[(ncol + n8*8 + g)*WP + k16*8 + tg*2]);  // (b0, b1)
                mma_f16(acc[n8][0], acc[n8][1], acc[n8][2], acc[n8][3],
                        aLo.x, aHi.x, aLo.y, aHi.y, bb.x, bb.y);
            }
        }
        cur ^= 1;
    }

    // ---- epilogue: bias (+ sigmoid), write out
    const int r0 = tile + mrow + g;
    const int r1 = r0 + 8;
    #pragma unroll
    for (int n8 = 0; n8 < O2/8; ++n8) {
        int c0 = ncol + n8*8 + 2*tg;
        int c1 = c0 + 1;
        float bz0 = bias[c0], bz1 = bias[c1];
        float v00 = acc[n8][0] + bz0;
        float v01 = acc[n8][1] + bz1;
        float v10 = acc[n8][2] + bz0;
        float v11 = acc[n8][3] + bz1;
        if (SIG) {
            v00 = 1.f/(1.f + __expf(-v00));
            v01 = 1.f/(1.f + __expf(-v01));
            v10 = 1.f/(1.f + __expf(-v10));
            v11 = 1.f/(1.f + __expf(-v11));
        }
        if (sizeof(OutT) == 2) {   // half2 pair store (c0 even)
            if (r0 < NN) *reinterpret_cast<__half2*>(
                (__half*)out + (size_t)r0*O + c0) = __floats2half2_rn(v00, v01);
            if (r1 < NN) *reinterpret_cast<__half2*>(
                (__half*)out + (size_t)r1*O + c0) = __floats2half2_rn(v10, v11);
        } else {
            if (r0 < NN) { ((float*)out)[(size_t)r0*O + c0] = v00;
                           ((float*)out)[(size_t)r0*O + c1] = v01; }
            if (r1 < NN) { ((float*)out)[(size_t)r1*O + c0] = v10;
                           ((float*)out)[(size_t)r1*O + c1] = v11; }
        }
    }
}

// ---------------- launch ----------------------------------------------------
extern "C" void kernel_launch(void* const* d_in, const int* in_sizes, int n_in,
                              void* d_out, int out_size) {
    const float* x    = (const float*)d_in[0];
    const int*   esrc = (const int*)  d_in[1];
    const int*   edst = (const int*)  d_in[2];
    const int*   etyp = (const int*)  d_in[3];
    const float* W1   = (const float*)d_in[4];
    const float* r1   = (const float*)d_in[5];
    const float* b1   = (const float*)d_in[6];
    const float* W2   = (const float*)d_in[7];
    const float* r2   = (const float*)d_in[8];
    const float* b2   = (const float*)d_in[9];
    float* out = (float*)d_out;

    constexpr int SMEM_L1 = (128 + 2*128) * 72 * 4;  // 110592 B -> 2 CTAs/SM
    constexpr int SMEM_L2 = (128 + 2* 64) * 72 * 4;  //  73728 B -> 2 CTAs/SM
    cudaFuncSetAttribute((const void*)k_layer<128,false,__half>,
                         cudaFuncAttributeMaxDynamicSharedMemorySize, SMEM_L1);
    cudaFuncSetAttribute((const void*)k_layer< 64,true ,float >,
                         cudaFuncAttributeMaxDynamicSharedMemorySize, SMEM_L2);

    void* p = nullptr;
    cudaGetSymbolAddress(&p, g_xh);  __half* xh  = (__half*)p;
    cudaGetSymbolAddress(&p, g_h);   __half* h   = (__half*)p;
    cudaGetSymbolAddress(&p, g_W1h); __half* w1h = (__half*)p;
    cudaGetSymbolAddress(&p, g_W2h); __half* w2h = (__half*)p;

    const int HB = (NE + 255)/256;
    const int T1 = ((RR+1)*DD*DD + 255)/256;
    const int T2 = ((RR+1)*64*DD + 255)/256;
    const int XC = (NN*DD/4 + 255)/256;
    k_pre    <<<HB + T1 + T2 + XC, 256>>>(edst, etyp, x, W1, r1, W2, r2); // launch 0
    k_scan   <<<NBLK,             1024>>>();                               // launch 1
    k_scatter<<<(NE+255)/256,      256>>>(esrc, edst, etyp);               // launch 2

    k_layer<128,false,__half><<<(NN+127)/128, 512, SMEM_L1>>>(xh, w1h, b1, h);   // launch 3
    k_layer< 64,true ,float ><<<(NN+127)/128, 512, SMEM_L2>>>(h,  w2h, b2, out); // launch 4
}

// round 14
// speedup vs baseline: 1.4571x; 1.0547x over previous
#include <cuda_runtime.h>
#include <cuda_fp16.h>
#include <math.h>
#include <stdint.h>

#define NN 50000
#define NE 640000
#define RR 8
#define DD 128
#define NRSEG (NN*RR)
#define NBLK ((NRSEG + 1023)/1024)

// ---------------- scratch (device globals; no allocations allowed) ----------
__device__ int    g_cnt[NRSEG];          // zero at load; self-zeroed by k_scatter
__device__ int    g_off[NRSEG];
__device__ int    g_cur[NRSEG];
__device__ unsigned long long g_tstat[NBLK];  // lookback flags; reset by k_scatter
__device__ int2   g_sd[NE];              // (src, dst) packed, CSR order
__device__ __half g_xh[NN*DD];           // x pre-converted to half
__device__ __half g_h[NN*DD];            // layer1 output (half)
__device__ __half g_W1h[(RR+1)*DD*DD];   // [chunk][n][k-permuted] half
__device__ __half g_W2h[(RR+1)*64*DD];

// k-permutation within each 16-group: slot order packs (2t,2t+1,2t+8,2t+9)
// adjacent so one LDS.64 yields both fp16-MMA fragments.
__device__ __forceinline__ int slot16(int c) {
    return ((c & 7) >> 1)*4 + (c & 1) + ((c & 8) >> 3)*2;
}

#define CP_ASYNC16(smem_u32, gptr) \
    asm volatile("cp.async.cg.shared.global [%0], [%1], 16;" \
                 :: "r"(smem_u32), "l"(gptr) : "memory")
#define CP_COMMIT()  asm volatile("cp.async.commit_group;" ::: "memory")
#define CP_WAIT0()   asm volatile("cp.async.wait_group 0;" ::: "memory")

// ---------------- prelude: hist + weight cvt/permute + x cvt fused -----------
// seg ordering is RELATION-MAJOR: seg = rel*NN + node, so each row-block x rel
// owns one contiguous edge slice sorted by dst.
__global__ void k_pre(const int* __restrict__ dst, const int* __restrict__ typ,
                      const float* __restrict__ x,
                      const float* __restrict__ W1, const float* __restrict__ r1,
                      const float* __restrict__ W2, const float* __restrict__ r2) {
    const int HB = (NE + 255)/256;
    const int T1 = ((RR+1)*DD*DD + 255)/256;
    const int T2 = ((RR+1)*64*DD + 255)/256;
    int b = blockIdx.x;
    if (b < HB) {
        int e = b*256 + threadIdx.x;
        if (e < NE) atomicAdd(&g_cnt[typ[e]*NN + dst[e]], 1);
    } else if (b < HB + T1) {
        int idx = (b - HB)*256 + threadIdx.x;
        if (idx < (RR+1)*DD*DD) {
            int chunk = idx / (DD*DD);
            int rem   = idx - chunk*(DD*DD);
            int n = rem >> 7, k = rem & 127;
            float v = (chunk < RR) ? W1[(size_t)chunk*DD*DD + (size_t)k*DD + n]
                                   : r1[(size_t)k*DD + n];
            g_W1h[(size_t)chunk*DD*DD + n*DD + (k & ~15) + slot16(k & 15)] =
                __float2half_rn(v);
        }
    } else if (b < HB + T1 + T2) {
        int idx = (b - HB - T1)*256 + threadIdx.x;
        if (idx < (RR+1)*64*DD) {
            int chunk = idx / (64*DD);
            int rem   = idx - chunk*(64*DD);
            int n = rem >> 7, k = rem & 127;
            float v = (chunk < RR) ? W2[(size_t)chunk*DD*64 + (size_t)k*64 + n]
                                   : r2[(size_t)k*64 + n];
            g_W2h[(size_t)chunk*64*DD + n*DD + (k & ~15) + slot16(k & 15)] =
                __float2half_rn(v);
        }
    } else {
        // x -> half, 4 floats per thread
        int idx = (b - HB - T1 - T2)*256 + threadIdx.x;
        if (idx < NN*DD/4) {
            float4 xv = reinterpret_cast<const float4*>(x)[idx];
            __half2* o = reinterpret_cast<__half2*>(g_xh) + idx*2;
            o[0] = __floats2half2_rn(xv.x, xv.y);
            o[1] = __floats2half2_rn(xv.z, xv.w);
        }
    }
}

// ---------------- single-pass decoupled-lookback scan ------------------------
__global__ void __launch_bounds__(1024)
k_scan() {
    __shared__ int swarp[32];
    __shared__ int s_prefix;
    const int tid  = threadIdx.x;
    const int lane = tid & 31;
    const int wid  = tid >> 5;
    const int b    = blockIdx.x;
    const int i    = b*1024 + tid;

    int v = (i < NRSEG) ? g_cnt[i] : 0;

    int x = v;
    #pragma unroll
    for (int d = 1; d < 32; d <<= 1) {
        int t = __shfl_up_sync(0xffffffffu, x, d);
        if (lane >= d) x += t;
    }
    if (lane == 31) swarp[wid] = x;
    __syncthreads();
    if (wid == 0) {
        int y = swarp[lane];
        #pragma unroll
        for (int d = 1; d < 32; d <<= 1) {
            int t = __shfl_up_sync(0xffffffffu, y, d);
            if (lane >= d) y += t;
        }
        swarp[lane] = y;
    }
    __syncthreads();
    int incl = x + ((wid > 0) ? swarp[wid-1] : 0);
    int blocksum = swarp[31];

    if (tid == 0) {
        if (b == 0) {
            atomicExch(&g_tstat[0], (2ULL<<32) | (unsigned)blocksum);
            s_prefix = 0;
        } else {
            atomicExch(&g_tstat[b], (1ULL<<32) | (unsigned)blocksum);
            int run = 0;
            int j = b - 1;
            while (true) {
                unsigned long long f = atomicAdd(&g_tstat[j], 0ULL);
                unsigned st = (unsigned)(f >> 32);
                if (st == 0) { __nanosleep(40); continue; }
                run += (int)(unsigned)(f & 0xffffffffu);
                if (st == 2) break;
                --j;
            }
            atomicExch(&g_tstat[b], (2ULL<<32) | (unsigned)(run + blocksum));
            s_prefix = run;
        }
    }
    __syncthreads();
    if (i < NRSEG) {
        int o = s_prefix + incl - v;
        g_off[i] = o;
        g_cur[i] = o;
    }
}

__global__ void k_scatter(const int* __restrict__ src, const int* __restrict__ dst,
                          const int* __restrict__ typ) {
    int e = blockIdx.x*blockDim.x + threadIdx.x;
    if (e < NE) {
        int d = dst[e];
        int seg = typ[e]*NN + d;
        int pos = atomicAdd(&g_cur[seg], 1);
        g_sd[pos] = make_int2(src[e], d);
    }
    if (e < NRSEG) g_cnt[e] = 0;
    if (e < NBLK)  g_tstat[e] = 0ULL;
}

// ---------------- fused aggregate + GEMM layer (fp16 MMA) -------------------
__device__ __forceinline__ void mma_f16(float& c0, float& c1, float& c2, float& c3,
                                        uint32_t a0, uint32_t a1, uint32_t a2, uint32_t a3,
                                        uint32_t b0, uint32_t b1) {
    asm volatile(
        "mma.sync.aligned.m16n8k16.row.col.f32.f16.f16.f32 "
        "{%0,%1,%2,%3},{%4,%5,%6,%7},{%8,%9},{%0,%1,%2,%3};"
        : "+f"(c0), "+f"(c1), "+f"(c2), "+f"(c3)
        : "r"(a0), "r"(a1), "r"(a2), "r"(a3), "r"(b0), "r"(b1));
}

__device__ __forceinline__ uint32_t pack_h2(float x, float y) {
    __half2 h = __floats2half2_rn(x, y);
    return *reinterpret_cast<uint32_t*>(&h);
}
__device__ __forceinline__ float2 unpack_h2(uint32_t u) {
    __half2 h = *reinterpret_cast<__half2*>(&u);
    return __half22float2(h);
}
__device__ __forceinline__ uint32_t hadd2_u32(uint32_t a, uint32_t b) {
    __half2 r = __hadd2(*reinterpret_cast<__half2*>(&a),
                        *reinterpret_cast<__half2*>(&b));
    return *reinterpret_cast<uint32_t*>(&r);
}

// CTA = 128 nodes, 512 threads, 16 warps, 2 CTAs/SM (32 warps/SM, occ 50%).
// Node features half; sB double-buffered via cp.async (chunk r+1 fills while
// chunk r computes). Gather: pair {w, w+8} produces the 16 rows that both
// warps' MMA reads (grow = 16*(w&7) + 8*(w>>3)); run-accumulate in half2
// (SEL+HADD2 per word). gather->MMA sync is a pair-scoped named barrier.
// MMA: warp w computes rows [16*(w&7), +16) x cols [(w>>3)*O/2, +O/2).
template<int O, bool SIG, typename OutT>
__global__ void __launch_bounds__(512, 2)
k_layer(const __half* __restrict__ in,
        const __half* __restrict__ Wh,    // [9][O][DD] half, k-permuted
        const float* __restrict__ bias,
        OutT* __restrict__ out) {
    constexpr int TM = 128;
    constexpr int NT = 512;
    constexpr int WP = 72;     // half2 words per row (64 data + 8 pad)
    constexpr int O2 = O/2;

    extern __shared__ uint32_t smem[];
    uint32_t* sA = smem;                 // TM * WP
    uint32_t* sB0 = smem + TM*WP;        // O * WP (buffer 0)
    uint32_t* sB1 = sB0 + O*WP;          // O * WP (buffer 1)
    const uint32_t smem_u32 = (uint32_t)__cvta_generic_to_shared(smem);

    const int tid  = threadIdx.x;
    const int lane = tid & 31;
    const int wid  = tid >> 5;
    const int tile = blockIdx.x * TM;

    float acc[O2/8][4];
    #pragma unroll
    for (int n8 = 0; n8 < O2/8; ++n8) {
        acc[n8][0] = 0.f; acc[n8][1] = 0.f; acc[n8][2] = 0.f; acc[n8][3] = 0.f;
    }

    const int g  = lane >> 2;
    const int tg = lane & 3;
    const int mrow = (wid & 7) * 16;              // MMA row block
    const int ncol = (wid >> 3) * O2;             // MMA col block
    const int grow = (wid & 7)*16 + (wid >> 3)*8; // gather rows: pair covers mrow..+16
    const int pbar = 1 + (wid & 7);               // pair barrier id
    // lane's two half2 store slots (natural cols 4l..4l+3 under permutation)
    const int wbase = (lane >> 2)*8 + ((lane & 1) << 2) + ((lane & 2) >> 1);
    const __half* in_l = in + (lane << 2);    // lane-fixed column base

    // ---- cp.async fill helper (16B units): row n = u>>4, sub = u&15
    auto fill_sB = [&](int bufsel, int r) {
        const __half* Wp = Wh + (size_t)r*O*DD;
        uint32_t sbase = smem_u32 + (TM*WP + bufsel*O*WP)*4;
        #pragma unroll
        for (int u = tid; u < O*16; u += NT) {
            int n = u >> 4, sub = u & 15;
            CP_ASYNC16(sbase + (n*WP + sub*4)*4, Wp + n*DD + sub*8);
        }
        CP_COMMIT();
    };

    // prologue: prefetch chunk 0 into buffer 0
    fill_sB(0, 0);
    int cur = 0;

    for (int r = 0; r < RR + 1; ++r) {
        CP_WAIT0();
        __syncthreads();   // sB[cur] visible; prev MMA done with sA & sB[cur^1]
        if (r < RR) fill_sB(cur ^ 1, r + 1);   // overlap with gather + MMA

        // ================= gather: warp -> 8 rows (pair-private) =============
        if (r < RR) {
            // zero warp's 8 rows
            for (int w = lane; w < 8*WP; w += 32) sA[grow*WP + w] = 0u;

            // lane l (l<=8) holds boundary offset for row grow+l
            int bidx = r*NN + min(tile + grow + min(lane, 8), NN);
            int offv = (bidx < NRSEG) ? g_off[bidx] : NE;
            int es = __shfl_sync(0xffffffffu, offv, 0);
            int ee = __shfl_sync(0xffffffffu, offv, 8);

            uint32_t v01 = 0u, v23 = 0u;     // half2 run accumulators
            int currow = -1;
            for (int base = es; base < ee; base += 32) {
                const int m = min(ee - base, 32);
                // stage edge records: ONE coalesced LDG.64 for the warp
                int2 sdl = make_int2(0, 0);
                if (lane < m) sdl = g_sd[base + lane];
                // inner loop: register-resident addresses, LDG.64 rows,
                // half2 accumulate (SEL + HADD2 per word)
                #pragma unroll 4
                for (int j = 0; j < m; ++j) {
                    int src = __shfl_sync(0xffffffffu, sdl.x, j);
                    int row = __shfl_sync(0xffffffffu, sdl.y, j);
                    const uint2 u = *reinterpret_cast<const uint2*>(
                        in_l + (size_t)src*DD);
                    bool fresh = (row != currow);
                    currow = row;
                    v01 = fresh ? u.x : hadd2_u32(v01, u.x);
                    v23 = fresh ? u.y : hadd2_u32(v23, u.y);
                    int rw = (currow - tile)*WP;
                    sA[rw + wbase]     = v01;     // last write wins
                    sA[rw + wbase + 2] = v23;
                }
            }

            // post-pass: scale rows by 1/cnt in fp32 (per-row, cheap)
            #pragma unroll
            for (int i = 0; i < 8; ++i) {
                int c = __shfl_sync(0xffffffffu, offv, i+1)
                      - __shfl_sync(0xffffffffu, offv, i);
                if (c > 1) {
                    float inv = 1.f/(float)c;
                    int idx = (grow+i)*WP + wbase;
                    float2 u0 = unpack_h2(sA[idx]);
                    float2 u1 = unpack_h2(sA[idx+2]);
                    sA[idx]   = pack_h2(u0.x*inv, u0.y*inv);
                    sA[idx+2] = pack_h2(u1.x*inv, u1.y*inv);
                }
            }
        } else {
            // root chunk: direct half copy of input tile
            #pragma unroll
            for (int ii = 0; ii < 8; ++ii) {
                int node = tile + grow + ii;
                uint2 u = make_uint2(0u, 0u);
                if (node < NN)
                    u = *reinterpret_cast<const uint2*>(
                        in_l + (size_t)node*DD);
                int idx = (grow+ii)*WP + wbase;
                sA[idx]   = u.x;
                sA[idx+2] = u.y;
            }
        }
        // pair-scoped barrier: warps w and w+8 produced rows [mrow, mrow+16)
        asm volatile("bar.sync %0, 64;" :: "r"(pbar) : "memory");

        // ================= MMA (fp16, fp32 accum) =================
        const uint32_t* sBc = (cur == 0) ? sB0 : sB1;
        #pragma unroll
        for (int k16 = 0; k16 < DD/16; ++k16) {
            const uint2 aLo = *reinterpret_cast<const uint2*>(
                &sA[(mrow + g    )*WP + k16*8 + tg*2]);   // (a0, a2)
            const uint2 aHi = *reinterpret_cast<const uint2*>(
                &sA[(mrow + g + 8)*WP + k16*8 + tg*2]);   // (a1, a3)
            #pragma unroll
            for (int n8 = 0; n8 < O2/8; ++n8) {
                const uint2 bb = *reinterpret_cast<const uint2*>(
                    &sBc[(ncol + n8*8 + g)*WP + k16*8 + tg*2]);  // (b0, b1)
                mma_f16(acc[n8][0], acc[n8][1], acc[n8][2], acc[n8][3],
                        aLo.x, aHi.x, aLo.y, aHi.y, bb.x, bb.y);
            }
        }
        cur ^= 1;
    }

    // ---- epilogue: bias (+ sigmoid), write out
    const int r0 = tile + mrow + g;
    const int r1 = r0 + 8;
    #pragma unroll
    for (int n8 = 0; n8 < O2/8; ++n8) {
        int c0 = ncol + n8*8 + 2*tg;
        int c1 = c0 + 1;
        float bz0 = bias[c0], bz1 = bias[c1];
        float v00 = acc[n8][0] + bz0;
        float v01 = acc[n8][1] + bz1;
        float v10 = acc[n8][2] + bz0;
        float v11 = acc[n8][3] + bz1;
        if (SIG) {
            v00 = 1.f/(1.f + __expf(-v00));
            v01 = 1.f/(1.f + __expf(-v01));
            v10 = 1.f/(1.f + __expf(-v10));
            v11 = 1.f/(1.f + __expf(-v11));
        }
        if (sizeof(OutT) == 2) {   // half2 pair store (c0 even)
            if (r0 < NN) *reinterpret_cast<__half2*>(
                (__half*)out + (size_t)r0*O + c0) = __floats2half2_rn(v00, v01);
            if (r1 < NN) *reinterpret_cast<__half2*>(
                (__half*)out + (size_t)r1*O + c0) = __floats2half2_rn(v10, v11);
        } else {
            if (r0 < NN) { ((float*)out)[(size_t)r0*O + c0] = v00;
                           ((float*)out)[(size_t)r0*O + c1] = v01; }
            if (r1 < NN) { ((float*)out)[(size_t)r1*O + c0] = v10;
                           ((float*)out)[(size_t)r1*O + c1] = v11; }
        }
    }
}

// ---------------- launch ----------------------------------------------------
extern "C" void kernel_launch(void* const* d_in, const int* in_sizes, int n_in,
                              void* d_out, int out_size) {
    const float* x    = (const float*)d_in[0];
    const int*   esrc = (const int*)  d_in[1];
    const int*   edst = (const int*)  d_in[2];
    const int*   etyp = (const int*)  d_in[3];
    const float* W1   = (const float*)d_in[4];
    const float* r1   = (const float*)d_in[5];
    const float* b1   = (const float*)d_in[6];
    const float* W2   = (const float*)d_in[7];
    const float* r2   = (const float*)d_in[8];
    const float* b2   = (const float*)d_in[9];
    float* out = (float*)d_out;

    constexpr int SMEM_L1 = (128 + 2*128) * 72 * 4;  // 110592 B -> 2 CTAs/SM
    constexpr int SMEM_L2 = (128 + 2* 64) * 72 * 4;  //  73728 B -> 2 CTAs/SM
    cudaFuncSetAttribute((const void*)k_layer<128,false,__half>,
                         cudaFuncAttributeMaxDynamicSharedMemorySize, SMEM_L1);
    cudaFuncSetAttribute((const void*)k_layer< 64,true ,float >,
                         cudaFuncAttributeMaxDynamicSharedMemorySize, SMEM_L2);

    void* p = nullptr;
    cudaGetSymbolAddress(&p, g_xh);  __half* xh  = (__half*)p;
    cudaGetSymbolAddress(&p, g_h);   __half* h   = (__half*)p;
    cudaGetSymbolAddress(&p, g_W1h); __half* w1h = (__half*)p;
    cudaGetSymbolAddress(&p, g_W2h); __half* w2h = (__half*)p;

    const int HB = (NE + 255)/256;
    const int T1 = ((RR+1)*DD*DD + 255)/256;
    const int T2 = ((RR+1)*64*DD + 255)/256;
    const int XC = (NN*DD/4 + 255)/256;
    k_pre    <<<HB + T1 + T2 + XC, 256>>>(edst, etyp, x, W1, r1, W2, r2); // launch 0
    k_scan   <<<NBLK,             1024>>>();                               // launch 1
    k_scatter<<<(NE+255)/256,      256>>>(esrc, edst, etyp);               // launch 2

    k_layer<128,false,__half><<<(NN+127)/128, 512, SMEM_L1>>>(xh, w1h, b1, h);   // launch 3
    k_layer< 64,true ,float ><<<(NN+127)/128, 512, SMEM_L2>>>(h,  w2h, b2, out); // launch 4
}